// round 12
// baseline (speedup 1.0000x reference)
#include <cuda_runtime.h>
#include <math_constants.h>

// MeanMaxPooling: N=4, E=64, L=512, D=256
// in[0]: doc_state    (N, L, D) float32
// in[1]: nodes_mapping(N, E, L) float32 (0/1)
// in[2]: nodes_len    (N, E)    float32
// out  : (N, E, 2*D)  float32  [0:D]=max over masked states (incl. 0), [D:2D]=mean
//
// Session-final config: CTA per (n,e), 16 warps, warp w owns tokens
// [32w,32w+32) x full D. Ballot compaction (no atomics/barriers pre-gather),
// one predicated batch of 4 tokens (8 indep LDG.128), single barrier,
// float4 merge by 128 threads. Measured floor: ~6.3us kernel
// (~5k-cyc launch/drain + mask RT + gather RT; no pipe above 14%).

#define N_ 4
#define E_ 64
#define L_ 512
#define D_ 256
#define NW 16           // warps per CTA; warp w owns tokens [32w, 32w+32), full D

__global__ __launch_bounds__(NW * 32, 2)
void meanmax_kernel(const float* __restrict__ doc_state,
                    const float* __restrict__ nodes_mapping,
                    const float* __restrict__ nodes_len,
                    float* __restrict__ out)
{
    const int ne   = blockIdx.x;      // (n, e) pair
    const int n    = ne >> 6;         // ne / E
    const int tid  = threadIdx.x;
    const int w    = tid >> 5;        // warp = 32-token chunk
    const int lane = tid & 31;

    __shared__ float4 s_sum[NW][64];  // [warp][d/4]  16 KB
    __shared__ float4 s_max[NW][64];  //              16 KB

    // each warp reads its own 32 mask values -> in-warp bitmask; no barrier needed
    const float mval = nodes_mapping[(size_t)ne * L_ + w * 32 + lane];
    unsigned mb = __ballot_sync(0xffffffffu, mval != 0.0f);

    const float4* doc4 = (const float4*)(doc_state + (size_t)n * L_ * D_);
    const int base = w * 32;

    float4 s0 = make_float4(0.f, 0.f, 0.f, 0.f), s1 = s0;
    float4 m0 = make_float4(-CUDART_INF_F, -CUDART_INF_F, -CUDART_INF_F, -CUDART_INF_F);
    float4 m1 = m0;

    // gather: batches of 4 tokens (8 independent predicated 16B loads)
    while (mb) {
        int  l[4];
        bool ok[4];
        #pragma unroll
        for (int j = 0; j < 4; ++j) {
            ok[j] = (mb != 0u);
            l[j]  = ok[j] ? (__ffs(mb) - 1) : 0;
            mb &= mb - 1u;
        }
        float4 a[4], b[4];
        #pragma unroll
        for (int j = 0; j < 4; ++j) {
            if (ok[j]) {
                const float4* p = doc4 + (size_t)(base + l[j]) * (D_ / 4);
                a[j] = p[lane];        // d = 4*lane .. 4*lane+3
                b[j] = p[32 + lane];   // d = 128+4*lane ..
            }
        }
        #pragma unroll
        for (int j = 0; j < 4; ++j) {
            if (ok[j]) {
                s0.x += a[j].x; s0.y += a[j].y; s0.z += a[j].z; s0.w += a[j].w;
                s1.x += b[j].x; s1.y += b[j].y; s1.z += b[j].z; s1.w += b[j].w;
                m0.x = fmaxf(m0.x, a[j].x); m0.y = fmaxf(m0.y, a[j].y);
                m0.z = fmaxf(m0.z, a[j].z); m0.w = fmaxf(m0.w, a[j].w);
                m1.x = fmaxf(m1.x, b[j].x); m1.y = fmaxf(m1.y, b[j].y);
                m1.z = fmaxf(m1.z, b[j].z); m1.w = fmaxf(m1.w, b[j].w);
            }
        }
    }

    s_sum[w][lane]      = s0;
    s_sum[w][32 + lane] = s1;
    s_max[w][lane]      = m0;
    s_max[w][32 + lane] = m1;
    __syncthreads();

    // merge 16 partials; threads 0-63 -> max half, 64-127 -> sum half
    if (tid < 128) {
        const bool is_max = (tid < 64);
        const int  j = is_max ? tid : (tid - 64);   // float4 slot, 0..63

        float4 r = is_max ? s_max[0][j] : s_sum[0][j];
        #pragma unroll
        for (int q = 1; q < NW; ++q) {
            const float4 p = is_max ? s_max[q][j] : s_sum[q][j];
            if (is_max) {
                r.x = fmaxf(r.x, p.x); r.y = fmaxf(r.y, p.y);
                r.z = fmaxf(r.z, p.z); r.w = fmaxf(r.w, p.w);
            } else {
                r.x += p.x; r.y += p.y; r.z += p.z; r.w += p.w;
            }
        }

        const float len = nodes_len[ne];
        float4* orow = (float4*)(out + (size_t)ne * (2 * D_));
        if (is_max) {
            if (len < (float)L_) {      // any masked-out token => 0 participates in max
                r.x = fmaxf(r.x, 0.f); r.y = fmaxf(r.y, 0.f);
                r.z = fmaxf(r.z, 0.f); r.w = fmaxf(r.w, 0.f);
            }
            orow[j] = r;
        } else {
            const float inv = 1.0f / ((len > 0.f) ? len : 1.f);
            r.x *= inv; r.y *= inv; r.z *= inv; r.w *= inv;
            orow[(D_ / 4) + j] = r;
        }
    }
}

extern "C" void kernel_launch(void* const* d_in, const int* in_sizes, int n_in,
                              void* d_out, int out_size)
{
    const float* doc_state     = (const float*)d_in[0];
    const float* nodes_mapping = (const float*)d_in[1];
    const float* nodes_len     = (const float*)d_in[2];
    float* out = (float*)d_out;

    meanmax_kernel<<<N_ * E_, NW * 32>>>(doc_state, nodes_mapping, nodes_len, out);
}

// round 13
// speedup vs baseline: 1.1058x; 1.1058x over previous
#include <cuda_runtime.h>
#include <math_constants.h>

// MeanMaxPooling: N=4, E=64, L=512, D=256
// in[0]: doc_state    (N, L, D) float32
// in[1]: nodes_mapping(N, E, L) float32 (0/1)
// in[2]: nodes_len    (N, E)    float32
// out  : (N, E, 2*D)  float32  [0:D]=max over masked states (incl. 0), [D:2D]=mean
//
// SESSION-FINAL champion (reproduced at 6.336us kernel twice, best 6.24us):
// CTA per (n,e), 16 warps, warp w owns tokens [32w,32w+32) x full D.
// Ballot compaction (no atomics/barriers pre-gather), one predicated batch of
// 4 tokens (8 indep LDG.128), single barrier, float4 merge by 128 threads.
// Floor = ~5k-cyc launch/drain + mask RT + gather RT; no pipe above 14%.

#define N_ 4
#define E_ 64
#define L_ 512
#define D_ 256
#define NW 16           // warps per CTA; warp w owns tokens [32w, 32w+32), full D

__global__ __launch_bounds__(NW * 32, 2)
void meanmax_kernel(const float* __restrict__ doc_state,
                    const float* __restrict__ nodes_mapping,
                    const float* __restrict__ nodes_len,
                    float* __restrict__ out)
{
    const int ne   = blockIdx.x;      // (n, e) pair
    const int n    = ne >> 6;         // ne / E
    const int tid  = threadIdx.x;
    const int w    = tid >> 5;        // warp = 32-token chunk
    const int lane = tid & 31;

    __shared__ float4 s_sum[NW][64];  // [warp][d/4]  16 KB
    __shared__ float4 s_max[NW][64];  //              16 KB

    // each warp reads its own 32 mask values -> in-warp bitmask; no barrier needed
    const float mval = nodes_mapping[(size_t)ne * L_ + w * 32 + lane];
    unsigned mb = __ballot_sync(0xffffffffu, mval != 0.0f);

    const float4* doc4 = (const float4*)(doc_state + (size_t)n * L_ * D_);
    const int base = w * 32;

    float4 s0 = make_float4(0.f, 0.f, 0.f, 0.f), s1 = s0;
    float4 m0 = make_float4(-CUDART_INF_F, -CUDART_INF_F, -CUDART_INF_F, -CUDART_INF_F);
    float4 m1 = m0;

    // gather: batches of 4 tokens (8 independent predicated 16B loads)
    while (mb) {
        int  l[4];
        bool ok[4];
        #pragma unroll
        for (int j = 0; j < 4; ++j) {
            ok[j] = (mb != 0u);
            l[j]  = ok[j] ? (__ffs(mb) - 1) : 0;
            mb &= mb - 1u;
        }
        float4 a[4], b[4];
        #pragma unroll
        for (int j = 0; j < 4; ++j) {
            if (ok[j]) {
                const float4* p = doc4 + (size_t)(base + l[j]) * (D_ / 4);
                a[j] = p[lane];        // d = 4*lane .. 4*lane+3
                b[j] = p[32 + lane];   // d = 128+4*lane ..
            }
        }
        #pragma unroll
        for (int j = 0; j < 4; ++j) {
            if (ok[j]) {
                s0.x += a[j].x; s0.y += a[j].y; s0.z += a[j].z; s0.w += a[j].w;
                s1.x += b[j].x; s1.y += b[j].y; s1.z += b[j].z; s1.w += b[j].w;
                m0.x = fmaxf(m0.x, a[j].x); m0.y = fmaxf(m0.y, a[j].y);
                m0.z = fmaxf(m0.z, a[j].z); m0.w = fmaxf(m0.w, a[j].w);
                m1.x = fmaxf(m1.x, b[j].x); m1.y = fmaxf(m1.y, b[j].y);
                m1.z = fmaxf(m1.z, b[j].z); m1.w = fmaxf(m1.w, b[j].w);
            }
        }
    }

    s_sum[w][lane]      = s0;
    s_sum[w][32 + lane] = s1;
    s_max[w][lane]      = m0;
    s_max[w][32 + lane] = m1;
    __syncthreads();

    // merge 16 partials; threads 0-63 -> max half, 64-127 -> sum half
    if (tid < 128) {
        const bool is_max = (tid < 64);
        const int  j = is_max ? tid : (tid - 64);   // float4 slot, 0..63

        float4 r = is_max ? s_max[0][j] : s_sum[0][j];
        #pragma unroll
        for (int q = 1; q < NW; ++q) {
            const float4 p = is_max ? s_max[q][j] : s_sum[q][j];
            if (is_max) {
                r.x = fmaxf(r.x, p.x); r.y = fmaxf(r.y, p.y);
                r.z = fmaxf(r.z, p.z); r.w = fmaxf(r.w, p.w);
            } else {
                r.x += p.x; r.y += p.y; r.z += p.z; r.w += p.w;
            }
        }

        const float len = nodes_len[ne];
        float4* orow = (float4*)(out + (size_t)ne * (2 * D_));
        if (is_max) {
            if (len < (float)L_) {      // any masked-out token => 0 participates in max
                r.x = fmaxf(r.x, 0.f); r.y = fmaxf(r.y, 0.f);
                r.z = fmaxf(r.z, 0.f); r.w = fmaxf(r.w, 0.f);
            }
            orow[j] = r;
        } else {
            const float inv = 1.0f / ((len > 0.f) ? len : 1.f);
            r.x *= inv; r.y *= inv; r.z *= inv; r.w *= inv;
            orow[(D_ / 4) + j] = r;
        }
    }
}

extern "C" void kernel_launch(void* const* d_in, const int* in_sizes, int n_in,
                              void* d_out, int out_size)
{
    const float* doc_state     = (const float*)d_in[0];
    const float* nodes_mapping = (const float*)d_in[1];
    const float* nodes_len     = (const float*)d_in[2];
    float* out = (float*)d_out;

    meanmax_kernel<<<N_ * E_, NW * 32>>>(doc_state, nodes_mapping, nodes_len, out);
}

// round 14
// speedup vs baseline: 1.1111x; 1.0048x over previous
#include <cuda_runtime.h>
#include <math_constants.h>

// MeanMaxPooling: N=4, E=64, L=512, D=256
// in[0]: doc_state    (N, L, D) float32
// in[1]: nodes_mapping(N, E, L) float32 (0/1)
// in[2]: nodes_len    (N, E)    float32
// out  : (N, E, 2*D)  float32  [0:D]=max over masked states (incl. 0), [D:2D]=mean
//
// SESSION-FINAL champion. Identical source measured 3x:
// kernel 6.336 / 6.336 / 5.92 us; wall 6.85 / 7.36 / 6.66 us (DVFS noise).
// CTA per (n,e), 16 warps, warp w owns tokens [32w,32w+32) x full D.
// Ballot compaction (no atomics/barriers pre-gather), one predicated batch of
// 4 tokens (8 indep LDG.128), single barrier, float4 merge by 128 threads.
// Floor = ~5k-cyc launch/drain + mask RT + gather RT; no pipe above 14%.

#define N_ 4
#define E_ 64
#define L_ 512
#define D_ 256
#define NW 16           // warps per CTA; warp w owns tokens [32w, 32w+32), full D

__global__ __launch_bounds__(NW * 32, 2)
void meanmax_kernel(const float* __restrict__ doc_state,
                    const float* __restrict__ nodes_mapping,
                    const float* __restrict__ nodes_len,
                    float* __restrict__ out)
{
    const int ne   = blockIdx.x;      // (n, e) pair
    const int n    = ne >> 6;         // ne / E
    const int tid  = threadIdx.x;
    const int w    = tid >> 5;        // warp = 32-token chunk
    const int lane = tid & 31;

    __shared__ float4 s_sum[NW][64];  // [warp][d/4]  16 KB
    __shared__ float4 s_max[NW][64];  //              16 KB

    // each warp reads its own 32 mask values -> in-warp bitmask; no barrier needed
    const float mval = nodes_mapping[(size_t)ne * L_ + w * 32 + lane];
    unsigned mb = __ballot_sync(0xffffffffu, mval != 0.0f);

    const float4* doc4 = (const float4*)(doc_state + (size_t)n * L_ * D_);
    const int base = w * 32;

    float4 s0 = make_float4(0.f, 0.f, 0.f, 0.f), s1 = s0;
    float4 m0 = make_float4(-CUDART_INF_F, -CUDART_INF_F, -CUDART_INF_F, -CUDART_INF_F);
    float4 m1 = m0;

    // gather: batches of 4 tokens (8 independent predicated 16B loads)
    while (mb) {
        int  l[4];
        bool ok[4];
        #pragma unroll
        for (int j = 0; j < 4; ++j) {
            ok[j] = (mb != 0u);
            l[j]  = ok[j] ? (__ffs(mb) - 1) : 0;
            mb &= mb - 1u;
        }
        float4 a[4], b[4];
        #pragma unroll
        for (int j = 0; j < 4; ++j) {
            if (ok[j]) {
                const float4* p = doc4 + (size_t)(base + l[j]) * (D_ / 4);
                a[j] = p[lane];        // d = 4*lane .. 4*lane+3
                b[j] = p[32 + lane];   // d = 128+4*lane ..
            }
        }
        #pragma unroll
        for (int j = 0; j < 4; ++j) {
            if (ok[j]) {
                s0.x += a[j].x; s0.y += a[j].y; s0.z += a[j].z; s0.w += a[j].w;
                s1.x += b[j].x; s1.y += b[j].y; s1.z += b[j].z; s1.w += b[j].w;
                m0.x = fmaxf(m0.x, a[j].x); m0.y = fmaxf(m0.y, a[j].y);
                m0.z = fmaxf(m0.z, a[j].z); m0.w = fmaxf(m0.w, a[j].w);
                m1.x = fmaxf(m1.x, b[j].x); m1.y = fmaxf(m1.y, b[j].y);
                m1.z = fmaxf(m1.z, b[j].z); m1.w = fmaxf(m1.w, b[j].w);
            }
        }
    }

    s_sum[w][lane]      = s0;
    s_sum[w][32 + lane] = s1;
    s_max[w][lane]      = m0;
    s_max[w][32 + lane] = m1;
    __syncthreads();

    // merge 16 partials; threads 0-63 -> max half, 64-127 -> sum half
    if (tid < 128) {
        const bool is_max = (tid < 64);
        const int  j = is_max ? tid : (tid - 64);   // float4 slot, 0..63

        float4 r = is_max ? s_max[0][j] : s_sum[0][j];
        #pragma unroll
        for (int q = 1; q < NW; ++q) {
            const float4 p = is_max ? s_max[q][j] : s_sum[q][j];
            if (is_max) {
                r.x = fmaxf(r.x, p.x); r.y = fmaxf(r.y, p.y);
                r.z = fmaxf(r.z, p.z); r.w = fmaxf(r.w, p.w);
            } else {
                r.x += p.x; r.y += p.y; r.z += p.z; r.w += p.w;
            }
        }

        const float len = nodes_len[ne];
        float4* orow = (float4*)(out + (size_t)ne * (2 * D_));
        if (is_max) {
            if (len < (float)L_) {      // any masked-out token => 0 participates in max
                r.x = fmaxf(r.x, 0.f); r.y = fmaxf(r.y, 0.f);
                r.z = fmaxf(r.z, 0.f); r.w = fmaxf(r.w, 0.f);
            }
            orow[j] = r;
        } else {
            const float inv = 1.0f / ((len > 0.f) ? len : 1.f);
            r.x *= inv; r.y *= inv; r.z *= inv; r.w *= inv;
            orow[(D_ / 4) + j] = r;
        }
    }
}

extern "C" void kernel_launch(void* const* d_in, const int* in_sizes, int n_in,
                              void* d_out, int out_size)
{
    const float* doc_state     = (const float*)d_in[0];
    const float* nodes_mapping = (const float*)d_in[1];
    const float* nodes_len     = (const float*)d_in[2];
    float* out = (float*)d_out;

    meanmax_kernel<<<N_ * E_, NW * 32>>>(doc_state, nodes_mapping, nodes_len, out);
}